// round 9
// baseline (speedup 1.0000x reference)
#include <cuda_runtime.h>
#include <cuda_fp16.h>
#include <cstdint>

// out[dst[e]] += edge_attr[e] * x[src[e]],  D=64 f32, indices int32.
// History: R2 atomic scatter 58us (REDG-bound). R4/R6 bucket+gather 47.6us.
// R7 fp16 x 46.8us (gather issue/latency-bound, 24.5us). R8 half-warp split
// REGRESSED (26.5us, SELs + halved MLP). R9: back to R7 shape (32 lanes x
// half2 per edge), but metadata via int4 (2 edges / 16B load), unroll 8
// edges/iter for MLP~12, 128-thread blocks for better retirement balance.
// LSU floor ~1.25 LDG/edge ~= 11us; predict ~18us gather.

#define BUCKET_CAP 192           // Poisson(40) over 25K bins: max ~85
#define MAX_CB     32768
#define MAX_NODES  131072

__device__ int   g_counts[MAX_CB];                        // zero-init, self-resetting
__device__ int2  g_bucket[(size_t)MAX_CB * BUCKET_CAP];   // {src, attr bits}; rows 16B-aligned
__device__ uint2 g_xh[(size_t)MAX_NODES * 16];            // x as fp16: [node][32] half2

// ---------- launch 1: convert x->fp16 (blocks [0,cvb)) + bucket fill ----------
__device__ __forceinline__ void _fill_one(int s, int d, float w,
                                          int n_coarse, int n_nodes) {
    if ((unsigned)d >= (unsigned)n_coarse) return;
    if ((unsigned)s >= (unsigned)n_nodes) { s = 0; w = 0.f; }
    int pos = atomicAdd(&g_counts[d], 1);
    if (pos < BUCKET_CAP)
        g_bucket[(unsigned)d * BUCKET_CAP + pos] = make_int2(s, __float_as_int(w));
    // overflow: true total stays in g_counts; gather rescans exactly.
}

__global__ void __launch_bounds__(256)
_prep_kernel(const float4* __restrict__ x4,
             const int* __restrict__ src, const int* __restrict__ dst,
             const float* __restrict__ attr,
             int num_edges, int n_coarse, int n_nodes,
             int cvb, int vec_ok) {
    if ((int)blockIdx.x < cvb) {
        int t = blockIdx.x * blockDim.x + threadIdx.x;
        int n16 = n_nodes * 16;
        if (t < n16) {
            float4 v = x4[t];
            __half2 h0 = __floats2half2_rn(v.x, v.y);
            __half2 h1 = __floats2half2_rn(v.z, v.w);
            uint2 u;
            u.x = *(const unsigned*)&h0;
            u.y = *(const unsigned*)&h1;
            g_xh[t] = u;
        }
        return;
    }
    int base = ((blockIdx.x - cvb) * blockDim.x + threadIdx.x) * 4;
    if (base >= num_edges) return;

    if (vec_ok && base + 4 <= num_edges) {
        int4   s4 = *(const int4*)(src + base);
        int4   d4 = *(const int4*)(dst + base);
        float4 w4 = *(const float4*)(attr + base);
        _fill_one(s4.x, d4.x, w4.x, n_coarse, n_nodes);
        _fill_one(s4.y, d4.y, w4.y, n_coarse, n_nodes);
        _fill_one(s4.z, d4.z, w4.z, n_coarse, n_nodes);
        _fill_one(s4.w, d4.w, w4.w, n_coarse, n_nodes);
    } else {
        int m = min(4, num_edges - base);
        for (int k = 0; k < m; k++) {
            int e = base + k;
            _fill_one(src[e], dst[e], attr[e], n_coarse, n_nodes);
        }
    }
}

// ---------- launch 2: gather-reduce, one warp per coarse node ----------
// 32 lanes x half2 per edge (R7 shape); int4 metadata (2 edges); unroll 8.
__device__ __forceinline__ void _acc2(float2& acc, const __half2* __restrict__ xh2,
                                      unsigned s, float wt, unsigned lane) {
    float2 v = __half22float2(xh2[s * 32u + lane]);
    acc.x = fmaf(wt, v.x, acc.x);
    acc.y = fmaf(wt, v.y, acc.y);
}

__global__ void __launch_bounds__(128)
_gather_kernel(const float2* __restrict__ x2,    // fp32 x (overflow path only)
               const int* __restrict__ src, const int* __restrict__ dst,
               const float* __restrict__ attr,
               float2* __restrict__ out2,         // [n_coarse, 32] float2
               int n_coarse, int n_nodes, int num_edges) {
    int w    = (blockIdx.x * blockDim.x + threadIdx.x) >> 5;
    unsigned lane = threadIdx.x & 31;
    if (w >= n_coarse) return;

    int raw_cnt = g_counts[w];
    float2 acc = make_float2(0.f, 0.f);
    const __half2* __restrict__ xh2 = (const __half2*)g_xh;

    if (raw_cnt <= BUCKET_CAP) {
        const int2* __restrict__ b = g_bucket + (unsigned)w * BUCKET_CAP;
        int i = 0;
        // 8 edges per iteration: 4 int4 metadata loads + 8 x loads in flight
        for (; i + 8 <= raw_cnt; i += 8) {
            int4 m0 = *(const int4*)(b + i);
            int4 m1 = *(const int4*)(b + i + 2);
            int4 m2 = *(const int4*)(b + i + 4);
            int4 m3 = *(const int4*)(b + i + 6);
            _acc2(acc, xh2, (unsigned)m0.x, __int_as_float(m0.y), lane);
            _acc2(acc, xh2, (unsigned)m0.z, __int_as_float(m0.w), lane);
            _acc2(acc, xh2, (unsigned)m1.x, __int_as_float(m1.y), lane);
            _acc2(acc, xh2, (unsigned)m1.z, __int_as_float(m1.w), lane);
            _acc2(acc, xh2, (unsigned)m2.x, __int_as_float(m2.y), lane);
            _acc2(acc, xh2, (unsigned)m2.z, __int_as_float(m2.w), lane);
            _acc2(acc, xh2, (unsigned)m3.x, __int_as_float(m3.y), lane);
            _acc2(acc, xh2, (unsigned)m3.z, __int_as_float(m3.w), lane);
        }
        for (; i + 2 <= raw_cnt; i += 2) {
            int4 m0 = *(const int4*)(b + i);
            _acc2(acc, xh2, (unsigned)m0.x, __int_as_float(m0.y), lane);
            _acc2(acc, xh2, (unsigned)m0.z, __int_as_float(m0.w), lane);
        }
        if (i < raw_cnt) {
            int2 p = b[i];
            _acc2(acc, xh2, (unsigned)p.x, __int_as_float(p.y), lane);
        }
    } else {
        // overflow (statistically never): exact fp32 rescan of the edge list
        for (int e = 0; e < num_edges; e++) {
            if (dst[e] == w) {
                int s = src[e];
                float wt = attr[e];
                if ((unsigned)s >= (unsigned)n_nodes) { s = 0; wt = 0.f; }
                float2 v = x2[(unsigned)s * 32u + lane];
                acc.x = fmaf(wt, v.x, acc.x);
                acc.y = fmaf(wt, v.y, acc.y);
            }
        }
    }

    out2[(unsigned)w * 32u + lane] = acc;

    if (lane == 0) g_counts[w] = 0;   // self-reset for next call
}

// ---------- fallback (shapes exceed scratch): atomic scatter, fp32 ----------
__global__ void _zero_out_kernel(float4* __restrict__ out, int n4) {
    int i = blockIdx.x * blockDim.x + threadIdx.x;
    if (i < n4) out[i] = make_float4(0.f, 0.f, 0.f, 0.f);
}

__global__ void __launch_bounds__(256)
_scatter_add_kernel(const float4* __restrict__ x4,
                    const int* __restrict__ src,
                    const int* __restrict__ dst,
                    const float* __restrict__ attr,
                    float* __restrict__ out,
                    int num_edges, int n_nodes, int n_coarse) {
    int t = blockIdx.x * blockDim.x + threadIdx.x;
    int e = t >> 4;
    int c = t & 15;
    if (e >= num_edges) return;
    int s = src[e];
    int d = dst[e];
    float w = attr[e];
    if ((unsigned)s >= (unsigned)n_nodes || (unsigned)d >= (unsigned)n_coarse) return;
    float4 v = x4[(long long)s * 16 + c];
    v.x *= w; v.y *= w; v.z *= w; v.w *= w;
    float* p = out + (long long)d * 64 + c * 4;
    asm volatile("red.global.add.v4.f32 [%0], {%1, %2, %3, %4};"
                 :: "l"(p), "f"(v.x), "f"(v.y), "f"(v.z), "f"(v.w)
                 : "memory");
}

extern "C" void kernel_launch(void* const* d_in, const int* in_sizes, int n_in,
                              void* d_out, int out_size) {
    const float* x    = (const float*)d_in[0];     // [n_nodes, 64] f32
    const int*   eidx = (const int*)d_in[1];       // [2, E] int32
    const float* attr = (const float*)d_in[2];     // [E] f32
    float*       out  = (float*)d_out;             // [n_coarse, 64] f32

    int num_edges = in_sizes[2];
    int n_nodes   = in_sizes[0] / 64;
    int n_coarse  = out_size / 64;
    const int* src = eidx;
    const int* dst = eidx + num_edges;

    if (n_coarse <= MAX_CB && n_nodes <= MAX_NODES) {
        int vec_ok = ((num_edges & 3) == 0) &&
                     ((((unsigned long long)(uintptr_t)eidx) & 15ull) == 0) &&
                     ((((unsigned long long)(uintptr_t)attr) & 15ull) == 0);

        int cvb = (n_nodes * 16 + 255) / 256;
        int flb = ((num_edges + 3) / 4 + 255) / 256;
        _prep_kernel<<<cvb + flb, 256>>>((const float4*)x, src, dst, attr,
                                         num_edges, n_coarse, n_nodes,
                                         cvb, vec_ok);

        int gblocks = (n_coarse * 32 + 127) / 128;    // 4 warps per block
        _gather_kernel<<<gblocks, 128>>>((const float2*)x, src, dst, attr,
                                         (float2*)out, n_coarse, n_nodes,
                                         num_edges);
    } else {
        int n4 = out_size / 4;
        _zero_out_kernel<<<(n4 + 255) / 256, 256>>>((float4*)out, n4);
        long long tt = (long long)num_edges * 16;
        _scatter_add_kernel<<<(int)((tt + 255) / 256), 256>>>(
            (const float4*)x, src, dst, attr, out, num_edges, n_nodes, n_coarse);
    }
}

// round 10
// speedup vs baseline: 1.0534x; 1.0534x over previous
#include <cuda_runtime.h>
#include <cuda_fp16.h>
#include <cstdint>

// out[dst[e]] += edge_attr[e] * x[src[e]],  D=64 f32, indices int32.
// History: R2 scatter 58us (REDG-bound). R4/R6 bucket+gather 47.6us.
// R7 fp16 gather 46.8us (gather 24.5us = local optimum; R8/R9 inner-loop
// variants both regressed). Remaining fat is structural: ~9us launch/gap
// overhead + serialized convert/fill.
// R10: ONE persistent kernel. Phase 1: 1/4 of blocks convert x->fp16 (DRAM
// bound) concurrently with 3/4 doing the bucket fill (L2-atomic bound).
// Software grid barrier (monotonic counter, replay-safe). Phase 2: R7's
// proven gather loop, grid-strided. Grid = SMs*6 with launch_bounds(256,6)
// so every block is wave-1 resident -> barrier cannot deadlock.

#define BUCKET_CAP 192           // Poisson(40) over 25K bins: max ~85
#define MAX_CB     32768
#define MAX_NODES  131072

__device__ int      g_counts[MAX_CB];                        // zero-init, self-resetting
__device__ int2     g_bucket[(size_t)MAX_CB * BUCKET_CAP];   // {src, attr bits}
__device__ uint2    g_xh[(size_t)MAX_NODES * 16];            // x as fp16: [node][32] half2
__device__ unsigned g_bar;                                   // monotonic barrier counter

// ---------------- helpers ----------------
__device__ __forceinline__ void _fill_one(int s, int d, float w,
                                          int n_coarse, int n_nodes) {
    if ((unsigned)d >= (unsigned)n_coarse) return;
    if ((unsigned)s >= (unsigned)n_nodes) { s = 0; w = 0.f; }
    int pos = atomicAdd(&g_counts[d], 1);
    if (pos < BUCKET_CAP)
        g_bucket[(unsigned)d * BUCKET_CAP + pos] = make_int2(s, __float_as_int(w));
    // overflow: true total stays in g_counts; gather rescans exactly.
}

__device__ __forceinline__ void _acc2(float2& acc, const __half2* __restrict__ xh2,
                                      unsigned s, float wt, unsigned lane) {
    float2 v = __half22float2(xh2[s * 32u + lane]);
    acc.x = fmaf(wt, v.x, acc.x);
    acc.y = fmaf(wt, v.y, acc.y);
}

// Replay-safe grid barrier: counter only ever increments; each call's blocks
// wait for the next multiple of gridDim.x. Requires all blocks resident.
__device__ __forceinline__ void _grid_barrier(unsigned nB) {
    __threadfence();
    __syncthreads();
    if (threadIdx.x == 0) {
        unsigned arrive;
        asm volatile("atom.add.release.gpu.u32 %0, [%1], 1;"
                     : "=r"(arrive) : "l"(&g_bar) : "memory");
        arrive += 1;
        unsigned target = ((arrive - 1) / nB + 1) * nB;
        unsigned cur;
        do {
            asm volatile("ld.acquire.gpu.u32 %0, [%1];"
                         : "=r"(cur) : "l"(&g_bar) : "memory");
        } while (cur < target);
    }
    __syncthreads();
}

// ---------------- fused persistent kernel ----------------
__global__ void __launch_bounds__(256, 6)
_fused_kernel(const float4* __restrict__ x4,     // x as [n_nodes*16] float4
              const float2* __restrict__ x2,     // fp32 x (overflow path)
              const int* __restrict__ src, const int* __restrict__ dst,
              const float* __restrict__ attr,
              float2* __restrict__ out2,          // [n_coarse, 32] float2
              int num_edges, int n_coarse, int n_nodes, int vec_ok) {
    const unsigned nB  = gridDim.x;
    const unsigned bid = blockIdx.x;
    const unsigned tid = threadIdx.x;

    // ---- phase 1: convert (blocks [0, convB)) || fill (rest) ----
    const unsigned convB = nB / 4;
    if (bid < convB) {
        int n16 = n_nodes * 16;
        for (int t = bid * 256 + tid; t < n16; t += convB * 256) {
            float4 v = x4[t];
            __half2 h0 = __floats2half2_rn(v.x, v.y);
            __half2 h1 = __floats2half2_rn(v.z, v.w);
            uint2 u;
            u.x = *(const unsigned*)&h0;
            u.y = *(const unsigned*)&h1;
            g_xh[t] = u;
        }
    } else {
        const unsigned fB = nB - convB;
        const unsigned fbid = bid - convB;
        int nchunks = (num_edges + 3) / 4;
        for (int ch = fbid * 256 + tid; ch < nchunks; ch += fB * 256) {
            int base = ch * 4;
            if (vec_ok && base + 4 <= num_edges) {
                int4   s4 = *(const int4*)(src + base);
                int4   d4 = *(const int4*)(dst + base);
                float4 w4 = *(const float4*)(attr + base);
                _fill_one(s4.x, d4.x, w4.x, n_coarse, n_nodes);
                _fill_one(s4.y, d4.y, w4.y, n_coarse, n_nodes);
                _fill_one(s4.z, d4.z, w4.z, n_coarse, n_nodes);
                _fill_one(s4.w, d4.w, w4.w, n_coarse, n_nodes);
            } else {
                int m = min(4, num_edges - base);
                for (int k = 0; k < m; k++) {
                    int e = base + k;
                    _fill_one(src[e], dst[e], attr[e], n_coarse, n_nodes);
                }
            }
        }
    }

    // ---- grid barrier: fill + convert complete ----
    _grid_barrier(nB);

    // ---- phase 2: gather, one warp per node (R7 inner loop) ----
    const __half2* __restrict__ xh2 = (const __half2*)g_xh;
    unsigned lane   = tid & 31;
    unsigned gwarp  = bid * 8 + (tid >> 5);
    unsigned nwarps = nB * 8;

    for (int w = gwarp; w < n_coarse; w += nwarps) {
        int raw_cnt = g_counts[w];
        float2 acc = make_float2(0.f, 0.f);

        if (raw_cnt <= BUCKET_CAP) {
            const int2* __restrict__ b = g_bucket + (unsigned)w * BUCKET_CAP;
            int i = 0;
            for (; i + 4 <= raw_cnt; i += 4) {
                int2 p0 = b[i], p1 = b[i + 1], p2 = b[i + 2], p3 = b[i + 3];
                _acc2(acc, xh2, (unsigned)p0.x, __int_as_float(p0.y), lane);
                _acc2(acc, xh2, (unsigned)p1.x, __int_as_float(p1.y), lane);
                _acc2(acc, xh2, (unsigned)p2.x, __int_as_float(p2.y), lane);
                _acc2(acc, xh2, (unsigned)p3.x, __int_as_float(p3.y), lane);
            }
            for (; i < raw_cnt; i++) {
                int2 p = b[i];
                _acc2(acc, xh2, (unsigned)p.x, __int_as_float(p.y), lane);
            }
        } else {
            // overflow (statistically never): exact fp32 rescan
            for (int e = 0; e < num_edges; e++) {
                if (dst[e] == w) {
                    int s = src[e];
                    float wt = attr[e];
                    if ((unsigned)s >= (unsigned)n_nodes) { s = 0; wt = 0.f; }
                    float2 v = x2[(unsigned)s * 32u + lane];
                    acc.x = fmaf(wt, v.x, acc.x);
                    acc.y = fmaf(wt, v.y, acc.y);
                }
            }
        }

        out2[(unsigned)w * 32u + lane] = acc;
        if (lane == 0) g_counts[w] = 0;   // self-reset for next call
    }
}

// ---------- fallback (shapes exceed scratch): atomic scatter, fp32 ----------
__global__ void _zero_out_kernel(float4* __restrict__ out, int n4) {
    int i = blockIdx.x * blockDim.x + threadIdx.x;
    if (i < n4) out[i] = make_float4(0.f, 0.f, 0.f, 0.f);
}

__global__ void __launch_bounds__(256)
_scatter_add_kernel(const float4* __restrict__ x4,
                    const int* __restrict__ src,
                    const int* __restrict__ dst,
                    const float* __restrict__ attr,
                    float* __restrict__ out,
                    int num_edges, int n_nodes, int n_coarse) {
    int t = blockIdx.x * blockDim.x + threadIdx.x;
    int e = t >> 4;
    int c = t & 15;
    if (e >= num_edges) return;
    int s = src[e];
    int d = dst[e];
    float w = attr[e];
    if ((unsigned)s >= (unsigned)n_nodes || (unsigned)d >= (unsigned)n_coarse) return;
    float4 v = x4[(long long)s * 16 + c];
    v.x *= w; v.y *= w; v.z *= w; v.w *= w;
    float* p = out + (long long)d * 64 + c * 4;
    asm volatile("red.global.add.v4.f32 [%0], {%1, %2, %3, %4};"
                 :: "l"(p), "f"(v.x), "f"(v.y), "f"(v.z), "f"(v.w)
                 : "memory");
}

extern "C" void kernel_launch(void* const* d_in, const int* in_sizes, int n_in,
                              void* d_out, int out_size) {
    const float* x    = (const float*)d_in[0];     // [n_nodes, 64] f32
    const int*   eidx = (const int*)d_in[1];       // [2, E] int32
    const float* attr = (const float*)d_in[2];     // [E] f32
    float*       out  = (float*)d_out;             // [n_coarse, 64] f32

    int num_edges = in_sizes[2];
    int n_nodes   = in_sizes[0] / 64;
    int n_coarse  = out_size / 64;
    const int* src = eidx;
    const int* dst = eidx + num_edges;

    if (n_coarse <= MAX_CB && n_nodes <= MAX_NODES) {
        int vec_ok = ((num_edges & 3) == 0) &&
                     ((((unsigned long long)(uintptr_t)eidx) & 15ull) == 0) &&
                     ((((unsigned long long)(uintptr_t)attr) & 15ull) == 0);

        int sms = 148;
        cudaDeviceGetAttribute(&sms, cudaDevAttrMultiProcessorCount, 0);
        int nB = sms * 6;       // launch_bounds(256,6) guarantees residency

        _fused_kernel<<<nB, 256>>>((const float4*)x, (const float2*)x,
                                   src, dst, attr, (float2*)out,
                                   num_edges, n_coarse, n_nodes, vec_ok);
    } else {
        int n4 = out_size / 4;
        _zero_out_kernel<<<(n4 + 255) / 256, 256>>>((float4*)out, n4);
        long long tt = (long long)num_edges * 16;
        _scatter_add_kernel<<<(int)((tt + 255) / 256), 256>>>(
            (const float4*)x, src, dst, attr, out, num_edges, n_nodes, n_coarse);
    }
}